// round 1
// baseline (speedup 1.0000x reference)
#include <cuda_runtime.h>

// Precomputed uniform (sample-independent) constants, filled by setup_kernel.
__device__ float g_cs[48];    // cos/sin of half-angles for the 6x4 layer RYs
__device__ float g_post[10];  // post_W[8], post_b[2]
__device__ float g_preb[4];   // pre_b

__global__ void setup_kernel(const float* __restrict__ qp,
                             const float* __restrict__ postW,
                             const float* __restrict__ postb,
                             const float* __restrict__ preb) {
    int t = threadIdx.x;
    if (t < 24) {
        // layer k (0..5), qubit w: theta = qp[(k+1)*4 + w] = qp[4 + t]
        float th = qp[4 + t] * 0.5f;
        g_cs[2 * t]     = cosf(th);
        g_cs[2 * t + 1] = sinf(th);
    }
    if (t < 8) g_post[t] = postW[t];
    if (t < 2) g_post[8 + t] = postb[t];
    if (t < 4) g_preb[t] = preb[t];
}

__device__ __forceinline__ float dot4acc(float acc, float4 a, float4 b) {
    acc = fmaf(a.x, b.x, acc);
    acc = fmaf(a.y, b.y, acc);
    acc = fmaf(a.z, b.z, acc);
    acc = fmaf(a.w, b.w, acc);
    return acc;
}

__global__ void __launch_bounds__(256, 2)
qnet_kernel(const float4* __restrict__ X,   // [B, 128] float4 view of [B,512]
            const float4* __restrict__ W4,  // [4, 128] float4 view of pre_W [4,512]
            float2* __restrict__ out,       // [B] float2 view of [B,2]
            int nChunks)                    // B/32
{
    __shared__ float sh[64];  // [0:48) cs, [48:58) post, [58:62) pre_b
    int t = threadIdx.x;
    if (t < 48) sh[t] = g_cs[t];
    else if (t < 58) sh[t] = g_post[t - 48];
    else if (t < 62) sh[t] = g_preb[t - 58];
    __syncthreads();

    const int lane = t & 31;
    const int warpsPerBlock = blockDim.x >> 5;
    const int gwarp = blockIdx.x * warpsPerBlock + (t >> 5);
    const int totalWarps = gridDim.x * warpsPerBlock;

    // Per-lane register slice of pre_W: k = 4*lane + 128*i + {0..3}, 4 outputs.
    float4 wv[4][4];
#pragma unroll
    for (int o = 0; o < 4; o++)
#pragma unroll
        for (int i = 0; i < 4; i++)
            wv[o][i] = W4[o * 128 + 32 * i + lane];

    const float pb0 = sh[58], pb1 = sh[59], pb2 = sh[60], pb3 = sh[61];

    for (int chunk = gwarp; chunk < nChunks; chunk += totalWarps) {
        const size_t m0 = (size_t)chunk << 5;  // 32 samples per chunk

        float r0 = 0.f, r1 = 0.f, r2 = 0.f, r3 = 0.f;  // this lane's sample pre-acts

#pragma unroll 1
        for (int sb = 0; sb < 32; sb += 2) {
            const float4* xpA = X + (m0 + sb) * 128 + lane;
            float4 xa[4], xb[4];
#pragma unroll
            for (int i = 0; i < 4; i++) xa[i] = __ldcs(xpA + 32 * i);
#pragma unroll
            for (int i = 0; i < 4; i++) xb[i] = __ldcs(xpA + 128 + 32 * i);

            float a0 = 0, a1 = 0, a2 = 0, a3 = 0;
            float b0 = 0, b1 = 0, b2 = 0, b3 = 0;
#pragma unroll
            for (int i = 0; i < 4; i++) {
                a0 = dot4acc(a0, xa[i], wv[0][i]);
                a1 = dot4acc(a1, xa[i], wv[1][i]);
                a2 = dot4acc(a2, xa[i], wv[2][i]);
                a3 = dot4acc(a3, xa[i], wv[3][i]);
                b0 = dot4acc(b0, xb[i], wv[0][i]);
                b1 = dot4acc(b1, xb[i], wv[1][i]);
                b2 = dot4acc(b2, xb[i], wv[2][i]);
                b3 = dot4acc(b3, xb[i], wv[3][i]);
            }
#pragma unroll
            for (int off = 16; off; off >>= 1) {
                a0 += __shfl_xor_sync(0xffffffffu, a0, off);
                a1 += __shfl_xor_sync(0xffffffffu, a1, off);
                a2 += __shfl_xor_sync(0xffffffffu, a2, off);
                a3 += __shfl_xor_sync(0xffffffffu, a3, off);
                b0 += __shfl_xor_sync(0xffffffffu, b0, off);
                b1 += __shfl_xor_sync(0xffffffffu, b1, off);
                b2 += __shfl_xor_sync(0xffffffffu, b2, off);
                b3 += __shfl_xor_sync(0xffffffffu, b3, off);
            }
            if (lane == sb)     { r0 = a0; r1 = a1; r2 = a2; r3 = a3; }
            if (lane == sb + 1) { r0 = b0; r1 = b1; r2 = b2; r3 = b3; }
        }

        // ---- per-lane quantum circuit for sample m0 + lane ----
        float cw[4], sw[4];
        {
            float pre[4] = {r0 + pb0, r1 + pb1, r2 + pb2, r3 + pb3};
#pragma unroll
            for (int w = 0; w < 4; w++) {
                float e  = __expf(2.0f * pre[w]);
                float th = 1.0f - 2.0f / (e + 1.0f);        // tanh(pre)
                // half angle = tanh * (pi/2) * 0.5
                __sincosf(th * 0.78539816339744830961f, &sw[w], &cw[w]);
            }
        }

        // H|0>^4 = uniform 0.25; first RY layer on a product state:
        // st[idx] = 0.25 * prod_w (c_w -/+ s_w)
        float st[16];
        {
            float A0 = cw[0] - sw[0], B0 = cw[0] + sw[0];
            float A1 = cw[1] - sw[1], B1 = cw[1] + sw[1];
            float A2 = cw[2] - sw[2], B2 = cw[2] + sw[2];
            float A3 = cw[3] - sw[3], B3 = cw[3] + sw[3];
            float g[4] = {0.25f * A0 * A1, 0.25f * A0 * B1,
                          0.25f * B0 * A1, 0.25f * B0 * B1};
            float h[4] = {A2 * A3, A2 * B3, B2 * A3, B2 * B3};
#pragma unroll
            for (int a = 0; a < 4; a++)
#pragma unroll
                for (int b = 0; b < 4; b++)
                    st[4 * a + b] = g[a] * h[b];
        }

        // qubit w -> bit (8 >> w). 6 layers of CNOT(0,1),CNOT(2,3),CNOT(1,2), RYs.
#pragma unroll
        for (int k = 0; k < 6; k++) {
            // CNOT(0,1): control bit8, target bit4: swap st[8+j] <-> st[12+j]
#pragma unroll
            for (int j = 0; j < 4; j++) {
                float tmp = st[8 + j]; st[8 + j] = st[12 + j]; st[12 + j] = tmp;
            }
            // CNOT(2,3): control bit2, target bit1: swap (2,3),(6,7),(10,11),(14,15)
#pragma unroll
            for (int j = 0; j < 4; j++) {
                int i = 4 * j + 2;
                float tmp = st[i]; st[i] = st[i + 1]; st[i + 1] = tmp;
            }
            // CNOT(1,2): control bit4, target bit2: swap (4,6),(5,7),(12,14),(13,15)
            {
                float tmp;
                tmp = st[4];  st[4]  = st[6];  st[6]  = tmp;
                tmp = st[5];  st[5]  = st[7];  st[7]  = tmp;
                tmp = st[12]; st[12] = st[14]; st[14] = tmp;
                tmp = st[13]; st[13] = st[15]; st[15] = tmp;
            }
            // RY on each qubit with precomputed cos/sin (broadcast LDS)
#pragma unroll
            for (int w = 0; w < 4; w++) {
                float cc = sh[2 * (4 * k + w)];
                float ss = sh[2 * (4 * k + w) + 1];
                const int bit = 8 >> w;
#pragma unroll
                for (int i = 0; i < 16; i++) {
                    if ((i & bit) == 0) {
                        float s0 = st[i], s1 = st[i | bit];
                        st[i]       = fmaf(cc, s0, -ss * s1);
                        st[i | bit] = fmaf(ss, s0,  cc * s1);
                    }
                }
            }
        }

        // Measurement: z_w = sum_{bit_w=0} s^2 - sum_{bit_w=1} s^2 (fused into FMAs)
        float z0 = 0.f, z1 = 0.f, z2 = 0.f, z3 = 0.f;
#pragma unroll
        for (int i = 0; i < 16; i++) {
            float sp = st[i];
            z0 = fmaf((i & 8) ? -sp : sp, sp, z0);
            z1 = fmaf((i & 4) ? -sp : sp, sp, z1);
            z2 = fmaf((i & 2) ? -sp : sp, sp, z2);
            z3 = fmaf((i & 1) ? -sp : sp, sp, z3);
        }

        // post linear head
        float o0 = sh[48 + 8], o1 = sh[48 + 9];
        o0 = fmaf(sh[48 + 0], z0, o0);
        o0 = fmaf(sh[48 + 1], z1, o0);
        o0 = fmaf(sh[48 + 2], z2, o0);
        o0 = fmaf(sh[48 + 3], z3, o0);
        o1 = fmaf(sh[48 + 4], z0, o1);
        o1 = fmaf(sh[48 + 5], z1, o1);
        o1 = fmaf(sh[48 + 6], z2, o1);
        o1 = fmaf(sh[48 + 7], z3, o1);

        out[m0 + lane] = make_float2(o0, o1);
    }
}

extern "C" void kernel_launch(void* const* d_in, const int* in_sizes, int n_in,
                              void* d_out, int out_size) {
    const float* X     = (const float*)d_in[0];  // [B,512]
    const float* preW  = (const float*)d_in[1];  // [4,512]
    const float* preb  = (const float*)d_in[2];  // [4]
    const float* qp    = (const float*)d_in[3];  // [60]
    const float* postW = (const float*)d_in[4];  // [2,4]
    const float* postb = (const float*)d_in[5];  // [2]

    int B = in_sizes[0] / 512;
    int nChunks = B >> 5;

    setup_kernel<<<1, 64>>>(qp, postW, postb, preb);
    qnet_kernel<<<296, 256>>>((const float4*)X, (const float4*)preW,
                              (float2*)d_out, nChunks);
}